// round 1
// baseline (speedup 1.0000x reference)
#include <cuda_runtime.h>

#define CCH   192      // channels
#define LG    3        // gate channels
#define HWSZ  16384    // H*W
#define PIX   32       // pixels per block
#define KCH   32       // K chunk
#define NCHUNK 6       // 192/32
#define NTHR  192      // threads per block (one per output channel)
#define WST   193      // padded smem stride for transposed weights
#define EPSV  1e-6f

// ---- packed f32x2 helpers (Blackwell sm_103a) ----
__device__ __forceinline__ unsigned long long pack2(float a, float b) {
    unsigned long long r;
    asm("mov.b64 %0, {%1, %2};" : "=l"(r) : "f"(a), "f"(b));
    return r;
}
__device__ __forceinline__ void unpack2(unsigned long long v, float& a, float& b) {
    asm("mov.b64 {%0, %1}, %2;" : "=f"(a), "=f"(b) : "l"(v));
}
__device__ __forceinline__ void fma2(unsigned long long& d, unsigned long long a,
                                     unsigned long long b) {
    asm("fma.rn.f32x2 %0, %1, %2, %0;" : "+l"(d) : "l"(a), "l"(b));
}
__device__ __forceinline__ unsigned long long mul2(unsigned long long a,
                                                   unsigned long long b) {
    unsigned long long r;
    asm("mul.rn.f32x2 %0, %1, %2;" : "=l"(r) : "l"(a), "l"(b));
    return r;
}

// Dynamic smem layout (floats):
//   xs   [0,      6144)   x tile [c][p], stride 32
//   ctxs [6144,  12288)   ctx tile / t tile [c][p]
//   wA   [12288, 18464)   transposed weight chunk A (32 x 193)  (also LN stage [p][c])
//   wB   [18464, 24640)   transposed weight chunk B
//   gs   [24640, 24736)   gates [l][p]
//   mus  [24736, 24768)
//   rss  [24768, 24800)
#define SMEM_FLOATS 24800

__global__ void __launch_bounds__(NTHR, 2)
CM_29540785062535_kernel(const float* __restrict__ x,
                         const float* __restrict__ xl,
                         const float* __restrict__ fw,
                         const float* __restrict__ fb,
                         const float* __restrict__ hwm,
                         const float* __restrict__ hb,
                         const float* __restrict__ pw,
                         const float* __restrict__ pb,
                         const float* __restrict__ lnw,
                         const float* __restrict__ lnb,
                         float* __restrict__ out,
                         int Nn)
{
    extern __shared__ float smemf[];
    float* xs   = smemf;
    float* ctxs = smemf + 6144;
    float* wA   = smemf + 12288;
    float* wB   = smemf + 18464;
    float* gs   = smemf + 24640;
    float* mus  = smemf + 24736;
    float* rss  = smemf + 24768;

    const int t    = threadIdx.x;
    const int lane = t & 31;
    const int wid  = t >> 5;
    const int b    = blockIdx.x;
    const int n    = b >> 9;            // 512 tiles per image
    const int hw0  = (b & 511) << 5;

    const float* xb = x + ((size_t)n * CCH) * HWSZ + hw0;

    // ---- stage x tile (coalesced float4) ----
    #pragma unroll
    for (int j = 0; j < 8; ++j) {
        int f4 = t + j * NTHR;            // 0..1535
        int c = f4 >> 3, p4 = f4 & 7;
        float4 v = *reinterpret_cast<const float4*>(xb + (size_t)c * HWSZ + p4 * 4);
        *reinterpret_cast<float4*>(xs + c * PIX + p4 * 4) = v;
    }
    __syncthreads();

    // ---- gates: fx rows [C, C+L) ----
    if (t < LG * PIX) {
        int l = t >> 5, p = t & 31;
        const float* wrow = fw + (size_t)(CCH + l) * CCH;
        float acc = fb[CCH + l];
        #pragma unroll 8
        for (int k = 0; k < CCH; ++k)
            acc = fmaf(wrow[k], xs[k * PIX + p], acc);
        gs[l * PIX + p] = acc;
    }
    __syncthreads();

    // ---- ctx = sum_l gates[l] * x_list[l], streamed from HBM ----
    {
        float cacc[32];
        #pragma unroll
        for (int l = 0; l < LG; ++l) {
            const float* src = xl + ((size_t)(l * Nn + n) * CCH) * HWSZ + hw0;
            #pragma unroll
            for (int j = 0; j < 8; ++j) {
                int f4 = t + j * NTHR;
                int c = f4 >> 3, p4 = f4 & 7;
                float4 v = *reinterpret_cast<const float4*>(src + (size_t)c * HWSZ + p4 * 4);
                float g0 = gs[l * PIX + p4 * 4 + 0];
                float g1 = gs[l * PIX + p4 * 4 + 1];
                float g2 = gs[l * PIX + p4 * 4 + 2];
                float g3 = gs[l * PIX + p4 * 4 + 3];
                if (l == 0) {
                    cacc[j * 4 + 0] = g0 * v.x;
                    cacc[j * 4 + 1] = g1 * v.y;
                    cacc[j * 4 + 2] = g2 * v.z;
                    cacc[j * 4 + 3] = g3 * v.w;
                } else {
                    cacc[j * 4 + 0] = fmaf(g0, v.x, cacc[j * 4 + 0]);
                    cacc[j * 4 + 1] = fmaf(g1, v.y, cacc[j * 4 + 1]);
                    cacc[j * 4 + 2] = fmaf(g2, v.z, cacc[j * 4 + 2]);
                    cacc[j * 4 + 3] = fmaf(g3, v.w, cacc[j * 4 + 3]);
                }
            }
        }
        #pragma unroll
        for (int j = 0; j < 8; ++j) {
            int f4 = t + j * NTHR;
            int c = f4 >> 3, p4 = f4 & 7;
            *reinterpret_cast<float4*>(ctxs + c * PIX + p4 * 4) =
                make_float4(cacc[j * 4 + 0], cacc[j * 4 + 1],
                            cacc[j * 4 + 2], cacc[j * 4 + 3]);
        }
    }
    __syncthreads();

    // ---- q = f_w[:C] @ x, mod = h_w @ ctx  (thread t owns output channel t) ----
    unsigned long long accq[16], accm[16];
    {
        unsigned long long qb = pack2(fb[t], fb[t]);
        unsigned long long mb = pack2(hb[t], hb[t]);
        #pragma unroll
        for (int i = 0; i < 16; ++i) { accq[i] = qb; accm[i] = mb; }
    }

    for (int ch = 0; ch < NCHUNK; ++ch) {
        const int k0 = ch * KCH;
        // stage transposed weight chunks (coalesced LDG.128, padded STS)
        #pragma unroll
        for (int j = 0; j < 8; ++j) {
            int f4 = t + j * NTHR;
            int o = f4 >> 3, kq = f4 & 7;
            float4 a  = *reinterpret_cast<const float4*>(fw  + (size_t)o * CCH + k0 + kq * 4);
            float4 c2 = *reinterpret_cast<const float4*>(hwm + (size_t)o * CCH + k0 + kq * 4);
            wA[(kq * 4 + 0) * WST + o] = a.x;  wA[(kq * 4 + 1) * WST + o] = a.y;
            wA[(kq * 4 + 2) * WST + o] = a.z;  wA[(kq * 4 + 3) * WST + o] = a.w;
            wB[(kq * 4 + 0) * WST + o] = c2.x; wB[(kq * 4 + 1) * WST + o] = c2.y;
            wB[(kq * 4 + 2) * WST + o] = c2.z; wB[(kq * 4 + 3) * WST + o] = c2.w;
        }
        __syncthreads();

        #pragma unroll 8
        for (int kk = 0; kk < KCH; ++kk) {
            float wf = wA[kk * WST + t];
            float wh = wB[kk * WST + t];
            unsigned long long wf2 = pack2(wf, wf);
            unsigned long long wh2 = pack2(wh, wh);
            const ulonglong2* xr = reinterpret_cast<const ulonglong2*>(xs   + (k0 + kk) * PIX);
            const ulonglong2* cr = reinterpret_cast<const ulonglong2*>(ctxs + (k0 + kk) * PIX);
            #pragma unroll
            for (int q4 = 0; q4 < 8; ++q4) {
                ulonglong2 xv = xr[q4];
                ulonglong2 cv = cr[q4];
                fma2(accq[2 * q4 + 0], xv.x, wf2);
                fma2(accq[2 * q4 + 1], xv.y, wf2);
                fma2(accm[2 * q4 + 0], cv.x, wh2);
                fma2(accm[2 * q4 + 1], cv.y, wh2);
            }
        }
        __syncthreads();
    }

    // ---- t = q * mod, stored back into ctxs [c][p] ----
    #pragma unroll
    for (int i = 0; i < 16; ++i) {
        unsigned long long tv = mul2(accq[i], accm[i]);
        *reinterpret_cast<unsigned long long*>(ctxs + t * PIX + 2 * i) = tv;
    }
    __syncthreads();

    // ---- y = proj_w @ t ----
    {
        unsigned long long pb2 = pack2(pb[t], pb[t]);
        #pragma unroll
        for (int i = 0; i < 16; ++i) accq[i] = pb2;
    }
    for (int ch = 0; ch < NCHUNK; ++ch) {
        const int k0 = ch * KCH;
        #pragma unroll
        for (int j = 0; j < 8; ++j) {
            int f4 = t + j * NTHR;
            int o = f4 >> 3, kq = f4 & 7;
            float4 a = *reinterpret_cast<const float4*>(pw + (size_t)o * CCH + k0 + kq * 4);
            wA[(kq * 4 + 0) * WST + o] = a.x;  wA[(kq * 4 + 1) * WST + o] = a.y;
            wA[(kq * 4 + 2) * WST + o] = a.z;  wA[(kq * 4 + 3) * WST + o] = a.w;
        }
        __syncthreads();

        #pragma unroll 8
        for (int kk = 0; kk < KCH; ++kk) {
            float wp = wA[kk * WST + t];
            unsigned long long wp2 = pack2(wp, wp);
            const ulonglong2* tr = reinterpret_cast<const ulonglong2*>(ctxs + (k0 + kk) * PIX);
            #pragma unroll
            for (int q4 = 0; q4 < 8; ++q4) {
                ulonglong2 tv = tr[q4];
                fma2(accq[2 * q4 + 0], tv.x, wp2);
                fma2(accq[2 * q4 + 1], tv.y, wp2);
            }
        }
        __syncthreads();
    }

    // ---- LayerNorm stage: ts in [p][c] layout (reuse wA region) ----
    float* ts = wA;   // needs 32*192 = 6144 floats, wA(+into wB) has room
    #pragma unroll
    for (int i = 0; i < 16; ++i) {
        float y0, y1;
        unpack2(accq[i], y0, y1);
        ts[(2 * i + 0) * CCH + t] = y0;
        ts[(2 * i + 1) * CCH + t] = y1;
    }
    __syncthreads();

    // per-pixel mean / rstd via warp reductions (6 warps over 32 pixels)
    for (int p = wid; p < PIX; p += 6) {
        float s = 0.f, s2 = 0.f;
        #pragma unroll
        for (int i = 0; i < 6; ++i) {
            float v = ts[p * CCH + lane + 32 * i];
            s += v;
            s2 = fmaf(v, v, s2);
        }
        #pragma unroll
        for (int off = 16; off > 0; off >>= 1) {
            s  += __shfl_xor_sync(0xffffffffu, s, off);
            s2 += __shfl_xor_sync(0xffffffffu, s2, off);
        }
        if (lane == 0) {
            float mu  = s * (1.0f / CCH);
            float var = s2 * (1.0f / CCH) - mu * mu;
            mus[p] = mu;
            rss[p] = rsqrtf(var + EPSV);
        }
    }
    __syncthreads();

    // ---- normalize + residual, coalesced float4 store ----
    float* ob = out + ((size_t)n * CCH) * HWSZ + hw0;
    #pragma unroll
    for (int j = 0; j < 8; ++j) {
        int f4 = t + j * NTHR;
        int c = f4 >> 3, p4 = f4 & 7;
        int p0 = p4 * 4;
        float lw = lnw[c], lb = lnb[c];
        float4 r;
        r.x = lw * (ts[(p0 + 0) * CCH + c] - mus[p0 + 0]) * rss[p0 + 0] + lb + xs[c * PIX + p0 + 0];
        r.y = lw * (ts[(p0 + 1) * CCH + c] - mus[p0 + 1]) * rss[p0 + 1] + lb + xs[c * PIX + p0 + 1];
        r.z = lw * (ts[(p0 + 2) * CCH + c] - mus[p0 + 2]) * rss[p0 + 2] + lb + xs[c * PIX + p0 + 2];
        r.w = lw * (ts[(p0 + 3) * CCH + c] - mus[p0 + 3]) * rss[p0 + 3] + lb + xs[c * PIX + p0 + 3];
        *reinterpret_cast<float4*>(ob + (size_t)c * HWSZ + p0) = r;
    }
}

extern "C" void kernel_launch(void* const* d_in, const int* in_sizes, int n_in,
                              void* d_out, int out_size) {
    const float* x   = (const float*)d_in[0];
    const float* xl  = (const float*)d_in[1];
    const float* fw  = (const float*)d_in[2];
    const float* fb  = (const float*)d_in[3];
    const float* hwm = (const float*)d_in[4];
    const float* hb  = (const float*)d_in[5];
    const float* pw  = (const float*)d_in[6];
    const float* pb  = (const float*)d_in[7];
    const float* lnw = (const float*)d_in[8];
    const float* lnb = (const float*)d_in[9];
    float* out = (float*)d_out;

    int Nn = in_sizes[0] / (CCH * HWSZ);   // 16
    size_t smem = SMEM_FLOATS * sizeof(float);   // 99200 B

    cudaFuncSetAttribute(CM_29540785062535_kernel,
                         cudaFuncAttributeMaxDynamicSharedMemorySize, (int)smem);

    int blocks = Nn * (HWSZ / PIX);        // 16 * 512 = 8192
    CM_29540785062535_kernel<<<blocks, NTHR, smem>>>(
        x, xl, fw, fb, hwm, hb, pw, pb, lnw, lnb, out, Nn);
}

// round 2
// speedup vs baseline: 1.2946x; 1.2946x over previous
#include <cuda_runtime.h>

#define CCH   192
#define LG    3
#define HWSZ  16384
#define PIX   32
#define KCH   32
#define NCHUNK 6
#define NTHR  192
#define TSST  193      // padded stride for LN stage [p][c]
#define EPSV  1e-6f

typedef unsigned long long u64;

// ---- packed f32x2 helpers (Blackwell sm_103a) ----
__device__ __forceinline__ u64 pack2(float a, float b) {
    u64 r; asm("mov.b64 %0, {%1, %2};" : "=l"(r) : "f"(a), "f"(b)); return r;
}
__device__ __forceinline__ void unpack2(u64 v, float& a, float& b) {
    asm("mov.b64 {%0, %1}, %2;" : "=f"(a), "=f"(b) : "l"(v));
}
__device__ __forceinline__ void fma2(u64& d, u64 a, u64 b) {
    asm("fma.rn.f32x2 %0, %1, %2, %0;" : "+l"(d) : "l"(a), "l"(b));
}
__device__ __forceinline__ u64 mul2(u64 a, u64 b) {
    u64 r; asm("mul.rn.f32x2 %0, %1, %2;" : "=l"(r) : "l"(a), "l"(b)); return r;
}

// Dynamic smem (floats):
//  xs    [0,     6144)   x tile [c][p] stride 32
//  ctxs  [6144, 12288)   ctx / t tile [c][p] stride 32
//  wA    [12288,18432)   weight chunk A, swizzled [k][o] (32x192)
//  wB    [18432,24576)   weight chunk B
//  ts  = overlay at 12288 (32 x 193 = 6176, spills harmlessly into wB)
//  gs    [24576,24672)   gates [l][p]
//  gp    [24672,24864)   gate partials
//  mus   [24864,24896)
//  rss   [24896,24928)
#define SMEM_FLOATS 24928

__global__ void __launch_bounds__(NTHR, 2)
CM_29540785062535_kernel(const float* __restrict__ x,
                         const float* __restrict__ xl,
                         const float* __restrict__ fw,
                         const float* __restrict__ fb,
                         const float* __restrict__ hwm,
                         const float* __restrict__ hb,
                         const float* __restrict__ pw,
                         const float* __restrict__ pb,
                         const float* __restrict__ lnw,
                         const float* __restrict__ lnb,
                         float* __restrict__ out,
                         int Nn)
{
    extern __shared__ float sm[];
    float* xs   = sm;
    float* ctxs = sm + 6144;
    float* wA   = sm + 12288;
    float* wB   = sm + 18432;
    float* ts   = sm + 12288;    // overlay (wA+start of wB), used after proj
    float* gs   = sm + 24576;
    float* gp   = sm + 24672;
    float* mus  = sm + 24864;
    float* rss  = sm + 24896;

    const int t    = threadIdx.x;
    const int pg   = t & 3;          // pixel group: pixels 8*pg .. 8*pg+7
    const int oq   = t >> 2;         // channel quad: channels 4*oq .. 4*oq+3
    const int lane = t & 31;
    const int wid  = t >> 5;
    const int b    = blockIdx.x;
    const int n    = b >> 9;
    const int hw0  = (b & 511) << 5;

    const float* xbase = x + ((size_t)n * CCH) * HWSZ + hw0;

    // ---- stage x tile ----
    #pragma unroll
    for (int j = 0; j < 8; ++j) {
        int f4 = t + j * NTHR;
        int c = f4 >> 3, p4 = f4 & 7;
        *reinterpret_cast<float4*>(xs + c * PIX + p4 * 4) =
            *reinterpret_cast<const float4*>(xbase + (size_t)c * HWSZ + p4 * 4);
    }
    __syncthreads();

    // ---- gates (split-k over 2 halves, all 192 threads) ----
    {
        int half = (t >= 96) ? 1 : 0;
        int idx  = t - half * 96;
        int l = idx >> 5, p = idx & 31;
        const float* wrow = fw + (size_t)(CCH + l) * CCH + half * 96;
        const float* xcol = xs + half * 96 * PIX + p;
        float a0 = 0.f, a1 = 0.f, a2 = 0.f, a3 = 0.f;
        #pragma unroll 4
        for (int k = 0; k < 96; k += 4) {
            a0 = fmaf(wrow[k + 0], xcol[(k + 0) * PIX], a0);
            a1 = fmaf(wrow[k + 1], xcol[(k + 1) * PIX], a1);
            a2 = fmaf(wrow[k + 2], xcol[(k + 2) * PIX], a2);
            a3 = fmaf(wrow[k + 3], xcol[(k + 3) * PIX], a3);
        }
        gp[t] = (a0 + a1) + (a2 + a3);
    }
    __syncthreads();
    if (t < LG * PIX) {
        int l = t >> 5, p = t & 31;
        gs[l * PIX + p] = gp[t] + gp[t + 96] + fb[CCH + l];
    }
    __syncthreads();

    // ---- ctx = sum_l gates[l] * x_list[l] (streamed) ----
    {
        float cacc[32];
        #pragma unroll
        for (int l = 0; l < LG; ++l) {
            const float* src = xl + ((size_t)(l * Nn + n) * CCH) * HWSZ + hw0;
            #pragma unroll
            for (int j = 0; j < 8; ++j) {
                int f4 = t + j * NTHR;
                int c = f4 >> 3, p4 = f4 & 7;
                float4 v = *reinterpret_cast<const float4*>(src + (size_t)c * HWSZ + p4 * 4);
                float g0 = gs[l * PIX + p4 * 4 + 0];
                float g1 = gs[l * PIX + p4 * 4 + 1];
                float g2 = gs[l * PIX + p4 * 4 + 2];
                float g3 = gs[l * PIX + p4 * 4 + 3];
                if (l == 0) {
                    cacc[j*4+0] = g0*v.x; cacc[j*4+1] = g1*v.y;
                    cacc[j*4+2] = g2*v.z; cacc[j*4+3] = g3*v.w;
                } else {
                    cacc[j*4+0] = fmaf(g0, v.x, cacc[j*4+0]);
                    cacc[j*4+1] = fmaf(g1, v.y, cacc[j*4+1]);
                    cacc[j*4+2] = fmaf(g2, v.z, cacc[j*4+2]);
                    cacc[j*4+3] = fmaf(g3, v.w, cacc[j*4+3]);
                }
            }
        }
        #pragma unroll
        for (int j = 0; j < 8; ++j) {
            int f4 = t + j * NTHR;
            int c = f4 >> 3, p4 = f4 & 7;
            *reinterpret_cast<float4*>(ctxs + c * PIX + p4 * 4) =
                make_float4(cacc[j*4+0], cacc[j*4+1], cacc[j*4+2], cacc[j*4+3]);
        }
    }
    __syncthreads();

    // ---- q = fw[:C] @ x ; mod = hw @ ctx  (4ch x 8px micro-tile / thread) ----
    u64 accq[16], accm[16];
    {
        float4 fb4 = *reinterpret_cast<const float4*>(fb + 4 * oq);
        float4 hb4 = *reinterpret_cast<const float4*>(hb + 4 * oq);
        u64 q0 = pack2(fb4.x, fb4.x), q1 = pack2(fb4.y, fb4.y);
        u64 q2 = pack2(fb4.z, fb4.z), q3 = pack2(fb4.w, fb4.w);
        u64 m0 = pack2(hb4.x, hb4.x), m1 = pack2(hb4.y, hb4.y);
        u64 m2 = pack2(hb4.z, hb4.z), m3 = pack2(hb4.w, hb4.w);
        #pragma unroll
        for (int i = 0; i < 4; ++i) {
            accq[0*4+i] = q0; accq[1*4+i] = q1; accq[2*4+i] = q2; accq[3*4+i] = q3;
            accm[0*4+i] = m0; accm[1*4+i] = m1; accm[2*4+i] = m2; accm[3*4+i] = m3;
        }
    }

    for (int ch = 0; ch < NCHUNK; ++ch) {
        const int k0 = ch * KCH;
        // stage both weight chunks, swizzled [k][4*(og^kq)+ol]
        #pragma unroll
        for (int j = 0; j < 8; ++j) {
            int f4 = t + j * NTHR;
            int o = f4 >> 3, kq = f4 & 7;
            float4 a  = *reinterpret_cast<const float4*>(fw  + (size_t)o * CCH + k0 + kq * 4);
            float4 h4 = *reinterpret_cast<const float4*>(hwm + (size_t)o * CCH + k0 + kq * 4);
            int sb = (((o >> 2) ^ kq) << 2) + (o & 3);
            wA[(4*kq+0)*CCH + sb] = a.x;  wA[(4*kq+1)*CCH + sb] = a.y;
            wA[(4*kq+2)*CCH + sb] = a.z;  wA[(4*kq+3)*CCH + sb] = a.w;
            wB[(4*kq+0)*CCH + sb] = h4.x; wB[(4*kq+1)*CCH + sb] = h4.y;
            wB[(4*kq+2)*CCH + sb] = h4.z; wB[(4*kq+3)*CCH + sb] = h4.w;
        }
        __syncthreads();

        #pragma unroll 4
        for (int kk = 0; kk < KCH; ++kk) {
            int widx = kk * CCH + ((oq ^ (kk >> 2)) << 2);
            float4 wf = *reinterpret_cast<const float4*>(wA + widx);
            float4 wh = *reinterpret_cast<const float4*>(wB + widx);
            const float* xr = xs   + (k0 + kk) * PIX + 8 * pg;
            const float* cr = ctxs + (k0 + kk) * PIX + 8 * pg;
            ulonglong2 xa = *reinterpret_cast<const ulonglong2*>(xr);
            ulonglong2 xb = *reinterpret_cast<const ulonglong2*>(xr + 4);
            ulonglong2 ca = *reinterpret_cast<const ulonglong2*>(cr);
            ulonglong2 cb = *reinterpret_cast<const ulonglong2*>(cr + 4);
            u64 w2;
            w2 = pack2(wf.x, wf.x);
            fma2(accq[0], xa.x, w2); fma2(accq[1], xa.y, w2);
            fma2(accq[2], xb.x, w2); fma2(accq[3], xb.y, w2);
            w2 = pack2(wf.y, wf.y);
            fma2(accq[4], xa.x, w2); fma2(accq[5], xa.y, w2);
            fma2(accq[6], xb.x, w2); fma2(accq[7], xb.y, w2);
            w2 = pack2(wf.z, wf.z);
            fma2(accq[8], xa.x, w2); fma2(accq[9], xa.y, w2);
            fma2(accq[10], xb.x, w2); fma2(accq[11], xb.y, w2);
            w2 = pack2(wf.w, wf.w);
            fma2(accq[12], xa.x, w2); fma2(accq[13], xa.y, w2);
            fma2(accq[14], xb.x, w2); fma2(accq[15], xb.y, w2);
            w2 = pack2(wh.x, wh.x);
            fma2(accm[0], ca.x, w2); fma2(accm[1], ca.y, w2);
            fma2(accm[2], cb.x, w2); fma2(accm[3], cb.y, w2);
            w2 = pack2(wh.y, wh.y);
            fma2(accm[4], ca.x, w2); fma2(accm[5], ca.y, w2);
            fma2(accm[6], cb.x, w2); fma2(accm[7], cb.y, w2);
            w2 = pack2(wh.z, wh.z);
            fma2(accm[8], ca.x, w2); fma2(accm[9], ca.y, w2);
            fma2(accm[10], cb.x, w2); fma2(accm[11], cb.y, w2);
            w2 = pack2(wh.w, wh.w);
            fma2(accm[12], ca.x, w2); fma2(accm[13], ca.y, w2);
            fma2(accm[14], cb.x, w2); fma2(accm[15], cb.y, w2);
        }
        __syncthreads();
    }

    // ---- t = q * mod, into ctxs [c][p], lane-rotated to avoid conflicts ----
    #pragma unroll
    for (int m = 0; m < 16; ++m) {
        int c  = m >> 2;
        int pp = (m + oq) & 3;
        int i  = c * 4 + pp;
        *reinterpret_cast<u64*>(ctxs + (4*oq + c) * PIX + 8*pg + 2*pp) =
            mul2(accq[i], accm[i]);
    }
    __syncthreads();

    // ---- y = proj_w @ t ----
    {
        float4 pb4 = *reinterpret_cast<const float4*>(pb + 4 * oq);
        u64 p0 = pack2(pb4.x, pb4.x), p1 = pack2(pb4.y, pb4.y);
        u64 p2 = pack2(pb4.z, pb4.z), p3 = pack2(pb4.w, pb4.w);
        #pragma unroll
        for (int i = 0; i < 4; ++i) {
            accq[0*4+i] = p0; accq[1*4+i] = p1; accq[2*4+i] = p2; accq[3*4+i] = p3;
        }
    }
    for (int ch = 0; ch < NCHUNK; ++ch) {
        const int k0 = ch * KCH;
        #pragma unroll
        for (int j = 0; j < 8; ++j) {
            int f4 = t + j * NTHR;
            int o = f4 >> 3, kq = f4 & 7;
            float4 a = *reinterpret_cast<const float4*>(pw + (size_t)o * CCH + k0 + kq * 4);
            int sb = (((o >> 2) ^ kq) << 2) + (o & 3);
            wA[(4*kq+0)*CCH + sb] = a.x;  wA[(4*kq+1)*CCH + sb] = a.y;
            wA[(4*kq+2)*CCH + sb] = a.z;  wA[(4*kq+3)*CCH + sb] = a.w;
        }
        __syncthreads();

        #pragma unroll 4
        for (int kk = 0; kk < KCH; ++kk) {
            int widx = kk * CCH + ((oq ^ (kk >> 2)) << 2);
            float4 wp = *reinterpret_cast<const float4*>(wA + widx);
            const float* tr = ctxs + (k0 + kk) * PIX + 8 * pg;
            ulonglong2 ta = *reinterpret_cast<const ulonglong2*>(tr);
            ulonglong2 tb = *reinterpret_cast<const ulonglong2*>(tr + 4);
            u64 w2;
            w2 = pack2(wp.x, wp.x);
            fma2(accq[0], ta.x, w2); fma2(accq[1], ta.y, w2);
            fma2(accq[2], tb.x, w2); fma2(accq[3], tb.y, w2);
            w2 = pack2(wp.y, wp.y);
            fma2(accq[4], ta.x, w2); fma2(accq[5], ta.y, w2);
            fma2(accq[6], tb.x, w2); fma2(accq[7], tb.y, w2);
            w2 = pack2(wp.z, wp.z);
            fma2(accq[8], ta.x, w2); fma2(accq[9], ta.y, w2);
            fma2(accq[10], tb.x, w2); fma2(accq[11], tb.y, w2);
            w2 = pack2(wp.w, wp.w);
            fma2(accq[12], ta.x, w2); fma2(accq[13], ta.y, w2);
            fma2(accq[14], tb.x, w2); fma2(accq[15], tb.y, w2);
        }
        __syncthreads();
    }

    // ---- LN stage: ts[p][c], stride 193, lane-rotated stores ----
    #pragma unroll
    for (int m = 0; m < 16; ++m) {
        int c   = m >> 2;
        int pp  = (m + oq) & 3;
        float y0, y1;
        unpack2(accq[c * 4 + pp], y0, y1);
        int px  = 8 * pg + 2 * pp;
        int col = 4 * oq + c;
        ts[px * TSST + col]       = y0;
        ts[(px + 1) * TSST + col] = y1;
    }
    __syncthreads();

    // ---- per-pixel mean / rstd ----
    for (int p = wid; p < PIX; p += 6) {
        float s = 0.f, s2 = 0.f;
        #pragma unroll
        for (int i = 0; i < 6; ++i) {
            float v = ts[p * TSST + lane + 32 * i];
            s += v;
            s2 = fmaf(v, v, s2);
        }
        #pragma unroll
        for (int off = 16; off > 0; off >>= 1) {
            s  += __shfl_xor_sync(0xffffffffu, s, off);
            s2 += __shfl_xor_sync(0xffffffffu, s2, off);
        }
        if (lane == 0) {
            float mu  = s * (1.0f / CCH);
            float var = s2 * (1.0f / CCH) - mu * mu;
            mus[p] = mu;
            rss[p] = rsqrtf(var + EPSV);
        }
    }
    __syncthreads();

    // ---- normalize + residual, coalesced store ----
    float* ob = out + ((size_t)n * CCH) * HWSZ + hw0;
    #pragma unroll
    for (int j = 0; j < 8; ++j) {
        int f4 = t + j * NTHR;
        int c = f4 >> 3, p4 = f4 & 7;
        int p0 = p4 * 4;
        float lw = lnw[c], lb = lnb[c];
        float4 xv = *reinterpret_cast<const float4*>(xs + c * PIX + p0);
        float4 r;
        r.x = lw * (ts[(p0+0)*TSST + c] - mus[p0+0]) * rss[p0+0] + lb + xv.x;
        r.y = lw * (ts[(p0+1)*TSST + c] - mus[p0+1]) * rss[p0+1] + lb + xv.y;
        r.z = lw * (ts[(p0+2)*TSST + c] - mus[p0+2]) * rss[p0+2] + lb + xv.z;
        r.w = lw * (ts[(p0+3)*TSST + c] - mus[p0+3]) * rss[p0+3] + lb + xv.w;
        *reinterpret_cast<float4*>(ob + (size_t)c * HWSZ + p0) = r;
    }
}

extern "C" void kernel_launch(void* const* d_in, const int* in_sizes, int n_in,
                              void* d_out, int out_size) {
    const float* x   = (const float*)d_in[0];
    const float* xl  = (const float*)d_in[1];
    const float* fw  = (const float*)d_in[2];
    const float* fb  = (const float*)d_in[3];
    const float* hwm = (const float*)d_in[4];
    const float* hb  = (const float*)d_in[5];
    const float* pw  = (const float*)d_in[6];
    const float* pb  = (const float*)d_in[7];
    const float* lnw = (const float*)d_in[8];
    const float* lnb = (const float*)d_in[9];
    float* out = (float*)d_out;

    int Nn = in_sizes[0] / (CCH * HWSZ);
    size_t smem = SMEM_FLOATS * sizeof(float);

    cudaFuncSetAttribute(CM_29540785062535_kernel,
                         cudaFuncAttributeMaxDynamicSharedMemorySize, (int)smem);

    int blocks = Nn * (HWSZ / PIX);
    CM_29540785062535_kernel<<<blocks, NTHR, smem>>>(
        x, xl, fw, fb, hwm, hb, pw, pb, lnw, lnb, out, Nn);
}